// round 1
// baseline (speedup 1.0000x reference)
#include <cuda_runtime.h>
#include <cuda_bf16.h>
#include <cstdint>

#define BATCH 2
#define SEQ   2048
#define HID   512
#define HEADS 8
#define HDIM  64
#define MAN   256
#define DM    512            // 2*MAN  (re || im)
#define NROWS (BATCH*SEQ)    // 4096
#define BH    (BATCH*HEADS)  // 16
#define SCALE 0.125f         // 64^-0.5

// ---------------- scratch (device globals; no allocations) ----------------
__device__ float g_xn[NROWS * HID];
__device__ float g_q_re[NROWS * HID];
__device__ float g_q_im[NROWS * HID];
__device__ float g_k_re[NROWS * HID];
__device__ float g_k_im[NROWS * HID];
__device__ float g_v_re[NROWS * HID];
__device__ float g_v_im[NROWS * HID];
__device__ float g_Qp[(size_t)BH * SEQ * DM];
__device__ float g_Kp[(size_t)BH * SEQ * DM];
__device__ float g_Vp[(size_t)BH * SEQ * DM];
__device__ float g_Op[(size_t)BH * SEQ * DM];
__device__ float g_oh_re[NROWS * HID];
__device__ float g_oh_im[NROWS * HID];

// ---------------- row L2-normalize ----------------
__global__ void norm_kernel(const float* __restrict__ x, float* __restrict__ xn) {
    int row = blockIdx.x;
    int t = threadIdx.x;                       // 128 threads, 4 floats each
    const float4* xr = (const float4*)(x + (size_t)row * HID);
    float4 v = xr[t];
    float ss = v.x*v.x + v.y*v.y + v.z*v.z + v.w*v.w;
    #pragma unroll
    for (int o = 16; o > 0; o >>= 1) ss += __shfl_xor_sync(0xffffffffu, ss, o);
    __shared__ float ws[4];
    if ((t & 31) == 0) ws[t >> 5] = ss;
    __syncthreads();
    float tot = ws[0] + ws[1] + ws[2] + ws[3];
    float inv = 1.0f / sqrtf(tot);
    v.x *= inv; v.y *= inv; v.z *= inv; v.w *= inv;
    ((float4*)(xn + (size_t)row * HID))[t] = v;
}

// ---------------- generic SGEMM: C(=|+=) sign * A@B ----------------
// A [M,K] row-major, B [K,N] row-major. C[r*ldc + c*cstride].
// 64x64 tile, BK=16, 16x16 threads, 4x4 micro-tile.
__global__ void sgemm_kernel(const float* __restrict__ A, const float* __restrict__ B,
                             float* __restrict__ C, int M, int N, int K,
                             int ldc, int cstride, int init, float sign) {
    __shared__ float As[16][64];
    __shared__ float Bs[16][64];
    int tx = threadIdx.x, ty = threadIdx.y;
    int tid = ty * 16 + tx;
    int row0 = blockIdx.y * 64;
    int col0 = blockIdx.x * 64;
    float acc[4][4] = {};
    for (int kt = 0; kt < K; kt += 16) {
        #pragma unroll
        for (int i = 0; i < 4; i++) {
            int idx = tid + i * 256;
            int r = idx >> 4, c = idx & 15;
            As[c][r] = A[(size_t)(row0 + r) * K + kt + c];
            int bk = idx >> 6, bn = idx & 63;
            Bs[bk][bn] = B[(size_t)(kt + bk) * N + col0 + bn];
        }
        __syncthreads();
        #pragma unroll
        for (int k = 0; k < 16; k++) {
            float a[4], b[4];
            #pragma unroll
            for (int i = 0; i < 4; i++) a[i] = As[k][ty * 4 + i];
            #pragma unroll
            for (int j = 0; j < 4; j++) b[j] = Bs[k][tx * 4 + j];
            #pragma unroll
            for (int i = 0; i < 4; i++)
                #pragma unroll
                for (int j = 0; j < 4; j++)
                    acc[i][j] += a[i] * b[j];
        }
        __syncthreads();
    }
    #pragma unroll
    for (int i = 0; i < 4; i++) {
        int r = row0 + ty * 4 + i;
        #pragma unroll
        for (int j = 0; j < 4; j++) {
            int c = col0 + tx * 4 + j;
            size_t o = (size_t)r * ldc + (size_t)c * cstride;
            float v = sign * acc[i][j];
            C[o] = init ? v : (C[o] + v);
        }
    }
}

// ---------------- manifold projection (complex, K=64) ----------------
// in: t_re,t_im [NROWS, 512]; W [64,256] re/im.  out Tp[(bh*SEQ+s)*512 + m] re, +256 im
__global__ void manifold_kernel(const float* __restrict__ t_re, const float* __restrict__ t_im,
                                const float* __restrict__ Wre, const float* __restrict__ Wim,
                                float* __restrict__ Tp) {
    // grid (4, 128, 16)  block (16,16): m-tile 64 (16 quads), s-tile 16
    __shared__ float sAr[16][64], sAi[16][64];
    __shared__ float4 sWr[64][16], sWi[64][16];
    int bh = blockIdx.z; int b = bh >> 3, h = bh & 7;
    int s0 = blockIdx.y * 16;
    int qbase = blockIdx.x * 16;               // quad offset into 64 quads (=256 m)
    int tx = threadIdx.x, ty = threadIdx.y;
    int tid = ty * 16 + tx;
    const float4* Wre4 = (const float4*)Wre;   // [64][64] quads
    const float4* Wim4 = (const float4*)Wim;
    #pragma unroll
    for (int i = 0; i < 4; i++) {
        int idx = tid + i * 256;
        int ss = idx >> 6, kk = idx & 63;
        size_t g = ((size_t)(b * SEQ + s0 + ss)) * HID + h * HDIM + kk;
        sAr[ss][kk] = t_re[g];
        sAi[ss][kk] = t_im[g];
        int wk = idx >> 4, mq = idx & 15;
        sWr[wk][mq] = Wre4[wk * 64 + qbase + mq];
        sWi[wk][mq] = Wim4[wk * 64 + qbase + mq];
    }
    __syncthreads();
    float4 ar = make_float4(0,0,0,0), ai = make_float4(0,0,0,0);
    #pragma unroll
    for (int k = 0; k < 64; k++) {
        float xr = sAr[ty][k], xi = sAi[ty][k];
        float4 wr = sWr[k][tx], wi = sWi[k][tx];
        ar.x += xr*wr.x - xi*wi.x;  ai.x += xr*wi.x + xi*wr.x;
        ar.y += xr*wr.y - xi*wi.y;  ai.y += xr*wi.y + xi*wr.y;
        ar.z += xr*wr.z - xi*wi.z;  ai.z += xr*wi.z + xi*wr.z;
        ar.w += xr*wr.w - xi*wi.w;  ai.w += xr*wi.w + xi*wr.w;
    }
    size_t o = ((size_t)bh * SEQ + s0 + ty) * DM + qbase * 4;
    ((float4*)(Tp + o))[tx] = ar;
    ((float4*)(Tp + o + MAN))[tx] = ai;
}

// ---------------- flash attention, d=512 real ----------------
// Q',K',V' [BH, SEQ, 512].  BQ=16, BK=16. 128 threads: qi=tid>>3, lane=tid&7.
__global__ void attn_kernel(const float* __restrict__ Qp, const float* __restrict__ Kp,
                            const float* __restrict__ Vp, float* __restrict__ Op) {
    extern __shared__ float smem[];
    float4* sK = (float4*)smem;          // 16*128 float4
    float4* sV = sK + 16 * 128;
    int bh = blockIdx.y;
    int q0 = blockIdx.x * 16;
    int tid = threadIdx.x;
    int qi = tid >> 3, lane = tid & 7;
    const float4* Qg = (const float4*)(Qp + ((size_t)bh * SEQ + q0 + qi) * DM);
    float4 qv[16];
    #pragma unroll
    for (int j = 0; j < 16; j++) qv[j] = Qg[j * 8 + lane];
    float4 acc[16];
    #pragma unroll
    for (int j = 0; j < 16; j++) acc[j] = make_float4(0,0,0,0);
    float m_run = -3.0e38f, l_run = 0.f;
    const float4* Kg = (const float4*)(Kp + (size_t)bh * SEQ * DM);
    const float4* Vg = (const float4*)(Vp + (size_t)bh * SEQ * DM);
    for (int t = 0; t < SEQ / 16; t++) {
        const float4* Ksrc = Kg + t * 16 * 128;
        const float4* Vsrc = Vg + t * 16 * 128;
        #pragma unroll
        for (int i = 0; i < 16; i++) {
            sK[tid + i * 128] = Ksrc[tid + i * 128];
            sV[tid + i * 128] = Vsrc[tid + i * 128];
        }
        __syncthreads();
        float p[16];
        float tm = -3.0e38f;
        #pragma unroll
        for (int k = 0; k < 16; k++) {
            float s = 0.f;
            const float4* kr = sK + k * 128;
            #pragma unroll
            for (int j = 0; j < 16; j++) {
                float4 kv = kr[j * 8 + lane];
                s += qv[j].x*kv.x + qv[j].y*kv.y + qv[j].z*kv.z + qv[j].w*kv.w;
            }
            s += __shfl_xor_sync(0xffffffffu, s, 1);
            s += __shfl_xor_sync(0xffffffffu, s, 2);
            s += __shfl_xor_sync(0xffffffffu, s, 4);
            s *= SCALE;
            p[k] = s;
            tm = fmaxf(tm, s);
        }
        float m_new = fmaxf(m_run, tm);
        float corr = __expf(m_run - m_new);
        float lsum = 0.f;
        #pragma unroll
        for (int k = 0; k < 16; k++) { p[k] = __expf(p[k] - m_new); lsum += p[k]; }
        l_run = l_run * corr + lsum;
        m_run = m_new;
        #pragma unroll
        for (int j = 0; j < 16; j++) {
            acc[j].x *= corr; acc[j].y *= corr; acc[j].z *= corr; acc[j].w *= corr;
        }
        #pragma unroll
        for (int k = 0; k < 16; k++) {
            float pk = p[k];
            const float4* vr = sV + k * 128;
            #pragma unroll
            for (int j = 0; j < 16; j++) {
                float4 vv = vr[j * 8 + lane];
                acc[j].x += pk*vv.x; acc[j].y += pk*vv.y;
                acc[j].z += pk*vv.z; acc[j].w += pk*vv.w;
            }
        }
        __syncthreads();
    }
    float inv = 1.f / l_run;
    float4* Og = (float4*)(Op + ((size_t)bh * SEQ + q0 + qi) * DM);
    #pragma unroll
    for (int j = 0; j < 16; j++) {
        float4 a = acc[j];
        a.x *= inv; a.y *= inv; a.z *= inv; a.w *= inv;
        Og[j * 8 + lane] = a;
    }
}

// ---------------- Wmi back-projection (complex, K=256) + head merge ----------------
// Op [(bh*SEQ+s)*512 + m] re, +256 im ; Wmi [256,64] -> o_re/o_im [NROWS,512]
__global__ void wmi_kernel(const float* __restrict__ Op,
                           const float* __restrict__ Wre, const float* __restrict__ Wim,
                           float* __restrict__ o_re, float* __restrict__ o_im) {
    // grid (128, 16) block (16,16): d-tile 64 (16 quads), s-tile 16, K chunked by 64
    __shared__ float sAr[16][64], sAi[16][64];
    __shared__ float4 sWr[64][16], sWi[64][16];
    int bh = blockIdx.y; int b = bh >> 3, h = bh & 7;
    int s0 = blockIdx.x * 16;
    int tx = threadIdx.x, ty = threadIdx.y;
    int tid = ty * 16 + tx;
    const float4* Wre4 = (const float4*)Wre;   // [256][16] quads
    const float4* Wim4 = (const float4*)Wim;
    float4 ar = make_float4(0,0,0,0), ai = make_float4(0,0,0,0);
    for (int kt = 0; kt < MAN; kt += 64) {
        #pragma unroll
        for (int i = 0; i < 4; i++) {
            int idx = tid + i * 256;
            int ss = idx >> 6, kk = idx & 63;
            size_t g = ((size_t)bh * SEQ + s0 + ss) * DM;
            sAr[ss][kk] = Op[g + kt + kk];
            sAi[ss][kk] = Op[g + MAN + kt + kk];
            int wk = idx >> 4, dq = idx & 15;
            sWr[wk][dq] = Wre4[(size_t)(kt + wk) * 16 + dq];
            sWi[wk][dq] = Wim4[(size_t)(kt + wk) * 16 + dq];
        }
        __syncthreads();
        #pragma unroll
        for (int k = 0; k < 64; k++) {
            float xr = sAr[ty][k], xi = sAi[ty][k];
            float4 wr = sWr[k][tx], wi = sWi[k][tx];
            ar.x += xr*wr.x - xi*wi.x;  ai.x += xr*wi.x + xi*wr.x;
            ar.y += xr*wr.y - xi*wi.y;  ai.y += xr*wi.y + xi*wr.y;
            ar.z += xr*wr.z - xi*wi.z;  ai.z += xr*wi.z + xi*wr.z;
            ar.w += xr*wr.w - xi*wi.w;  ai.w += xr*wi.w + xi*wr.w;
        }
        __syncthreads();
    }
    size_t o = ((size_t)(b * SEQ + s0 + ty)) * HID + h * HDIM;
    ((float4*)(o_re + o))[tx] = ar;
    ((float4*)(o_im + o))[tx] = ai;
}

// ---------------- launcher ----------------
extern "C" void kernel_launch(void* const* d_in, const int* in_sizes, int n_in,
                              void* d_out, int out_size) {
    const float* x      = (const float*)d_in[0];
    const float* Wq_re  = (const float*)d_in[1];
    const float* Wq_im  = (const float*)d_in[2];
    const float* Wk_re  = (const float*)d_in[3];
    const float* Wk_im  = (const float*)d_in[4];
    const float* Wv_re  = (const float*)d_in[5];
    const float* Wv_im  = (const float*)d_in[6];
    const float* Wm_re  = (const float*)d_in[7];
    const float* Wm_im  = (const float*)d_in[8];
    const float* Wmi_re = (const float*)d_in[9];
    const float* Wmi_im = (const float*)d_in[10];
    const float* Wo_re  = (const float*)d_in[11];
    const float* Wo_im  = (const float*)d_in[12];
    float* out = (float*)d_out;

    float *xn, *q_re, *q_im, *k_re, *k_im, *v_re, *v_im, *Qp, *Kp, *Vp, *Opp, *oh_re, *oh_im;
    cudaGetSymbolAddress((void**)&xn,    g_xn);
    cudaGetSymbolAddress((void**)&q_re,  g_q_re);
    cudaGetSymbolAddress((void**)&q_im,  g_q_im);
    cudaGetSymbolAddress((void**)&k_re,  g_k_re);
    cudaGetSymbolAddress((void**)&k_im,  g_k_im);
    cudaGetSymbolAddress((void**)&v_re,  g_v_re);
    cudaGetSymbolAddress((void**)&v_im,  g_v_im);
    cudaGetSymbolAddress((void**)&Qp,    g_Qp);
    cudaGetSymbolAddress((void**)&Kp,    g_Kp);
    cudaGetSymbolAddress((void**)&Vp,    g_Vp);
    cudaGetSymbolAddress((void**)&Opp,   g_Op);
    cudaGetSymbolAddress((void**)&oh_re, g_oh_re);
    cudaGetSymbolAddress((void**)&oh_im, g_oh_im);

    cudaFuncSetAttribute(attn_kernel, cudaFuncAttributeMaxDynamicSharedMemorySize,
                         2 * 16 * DM * (int)sizeof(float));

    norm_kernel<<<NROWS, 128>>>(x, xn);

    dim3 tb(16, 16);
    dim3 gq(HID / 64, NROWS / 64);
    sgemm_kernel<<<gq, tb>>>(xn, Wq_re, q_re, NROWS, HID, HID, HID, 1, 1, 1.f);
    sgemm_kernel<<<gq, tb>>>(xn, Wq_im, q_im, NROWS, HID, HID, HID, 1, 1, 1.f);
    sgemm_kernel<<<gq, tb>>>(xn, Wk_re, k_re, NROWS, HID, HID, HID, 1, 1, 1.f);
    sgemm_kernel<<<gq, tb>>>(xn, Wk_im, k_im, NROWS, HID, HID, HID, 1, 1, 1.f);
    sgemm_kernel<<<gq, tb>>>(xn, Wv_re, v_re, NROWS, HID, HID, HID, 1, 1, 1.f);
    sgemm_kernel<<<gq, tb>>>(xn, Wv_im, v_im, NROWS, HID, HID, HID, 1, 1, 1.f);

    dim3 gm(4, SEQ / 16, BH);
    manifold_kernel<<<gm, tb>>>(q_re, q_im, Wm_re, Wm_im, Qp);
    manifold_kernel<<<gm, tb>>>(k_re, k_im, Wm_re, Wm_im, Kp);
    manifold_kernel<<<gm, tb>>>(v_re, v_im, Wm_re, Wm_im, Vp);

    attn_kernel<<<dim3(SEQ / 16, BH), 128, 2 * 16 * DM * sizeof(float)>>>(Qp, Kp, Vp, Opp);

    wmi_kernel<<<dim3(SEQ / 16, BH), tb>>>(Opp, Wmi_re, Wmi_im, oh_re, oh_im);

    // out = (oh_re + i*oh_im) @ (Wo_re + i*Wo_im), interleaved [.,512,2]
    sgemm_kernel<<<gq, tb>>>(oh_re, Wo_re, out,     NROWS, HID, HID, 2 * HID, 2, 1,  1.f);
    sgemm_kernel<<<gq, tb>>>(oh_im, Wo_im, out,     NROWS, HID, HID, 2 * HID, 2, 0, -1.f);
    sgemm_kernel<<<gq, tb>>>(oh_re, Wo_im, out + 1, NROWS, HID, HID, 2 * HID, 2, 1,  1.f);
    sgemm_kernel<<<gq, tb>>>(oh_im, Wo_re, out + 1, NROWS, HID, HID, 2 * HID, 2, 0,  1.f);
}

// round 2
// speedup vs baseline: 4.8760x; 4.8760x over previous
#include <cuda_runtime.h>
#include <cuda_bf16.h>
#include <cstdint>

#define BATCH 2
#define SEQ   2048
#define HID   512
#define HEADS 8
#define HDIM  64
#define MAN   256
#define DM    512            // 2*MAN  (re || im)
#define NROWS (BATCH*SEQ)    // 4096
#define BH    (BATCH*HEADS)  // 16
#define SCALE 0.125f         // 64^-0.5

// ---------------- scratch (device globals; no allocations) ----------------
__device__ float g_xn[NROWS * HID];
__device__ float g_q_re[NROWS * HID];
__device__ float g_q_im[NROWS * HID];
__device__ float g_k_re[NROWS * HID];
__device__ float g_k_im[NROWS * HID];
__device__ float g_v_re[NROWS * HID];
__device__ float g_v_im[NROWS * HID];
__device__ float g_Qp[(size_t)BH * SEQ * DM];
__device__ float g_Kp[(size_t)BH * SEQ * DM];
__device__ float g_Vp[(size_t)BH * SEQ * DM];
__device__ float g_Op[(size_t)BH * SEQ * DM];
__device__ float g_oh_re[NROWS * HID];
__device__ float g_oh_im[NROWS * HID];
__device__ float g_S[(size_t)BH * SEQ * SEQ];   // 268 MB score/prob scratch

// ---------------- helpers ----------------
__device__ __forceinline__ float to_tf32(float x) {
    asm("cvt.rna.tf32.f32 %0, %1;" : "=f"(x) : "f"(x));
    return x;
}

__device__ __forceinline__ void mma_tf32(float c[4], const uint32_t a[4], const uint32_t b[2]) {
    asm volatile(
        "mma.sync.aligned.m16n8k8.row.col.f32.tf32.tf32.f32 "
        "{%0,%1,%2,%3},{%4,%5,%6,%7},{%8,%9},{%0,%1,%2,%3};"
        : "+f"(c[0]), "+f"(c[1]), "+f"(c[2]), "+f"(c[3])
        : "r"(a[0]), "r"(a[1]), "r"(a[2]), "r"(a[3]), "r"(b[0]), "r"(b[1]));
}

// ---------------- row L2-normalize ----------------
__global__ void norm_kernel(const float* __restrict__ x, float* __restrict__ xn) {
    int row = blockIdx.x;
    int t = threadIdx.x;                       // 128 threads, 4 floats each
    const float4* xr = (const float4*)(x + (size_t)row * HID);
    float4 v = xr[t];
    float ss = v.x*v.x + v.y*v.y + v.z*v.z + v.w*v.w;
    #pragma unroll
    for (int o = 16; o > 0; o >>= 1) ss += __shfl_xor_sync(0xffffffffu, ss, o);
    __shared__ float ws[4];
    if ((t & 31) == 0) ws[t >> 5] = ss;
    __syncthreads();
    float tot = ws[0] + ws[1] + ws[2] + ws[3];
    float inv = 1.0f / sqrtf(tot);
    v.x *= inv; v.y *= inv; v.z *= inv; v.w *= inv;
    ((float4*)(xn + (size_t)row * HID))[t] = v;
}

// ---------------- tf32 tensor-core GEMM ----------------
// C(=|+=) sign * A@B(^T).  A [M,K] rm.  TRANSB=0: B [K,N] rm.  TRANSB=1: B [N,K] rm (uses B^T).
// C[m*ldc + n*cstride].  Batched via blockIdx.z with element strides sA,sB,sC.
// 128x128 tile, BK=16, 256 threads (8 warps, 2x4 warp grid, 64x32 warp tiles).
template<int TRANSB>
__global__ __launch_bounds__(256)
void gemm_tf32(const float* __restrict__ A, const float* __restrict__ B, float* __restrict__ C,
               int M, int N, int K,
               size_t sA, size_t sB, size_t sC,
               int ldc, int cstride, int init, float sign) {
    __shared__ float As[16][136];   // [k][m], pad 8 -> conflict-free frag loads
    __shared__ float Bs[16][136];   // [k][n]

    const int tid = threadIdx.x;
    A += (size_t)blockIdx.z * sA;
    B += (size_t)blockIdx.z * sB;
    C += (size_t)blockIdx.z * sC;
    const int row0 = blockIdx.y * 128;
    const int col0 = blockIdx.x * 128;
    const int warp = tid >> 5, lane = tid & 31;
    const int wm = (warp & 1) * 64;       // warp m offset in tile
    const int wn = (warp >> 1) * 32;      // warp n offset in tile
    const int g = lane >> 2, tig = lane & 3;

    float c[4][4][4] = {};

    // register staging for gmem->smem (hides DRAM latency behind mma)
    float4 ra[2], rb[2];

    auto load_stage = [&](int kt) {
        #pragma unroll
        for (int i = 0; i < 2; i++) {
            int idx = tid + i * 256;
            int r = idx >> 2, kq = (idx & 3) * 4;
            ra[i] = *(const float4*)(A + (size_t)(row0 + r) * K + kt + kq);
        }
        if (TRANSB) {
            #pragma unroll
            for (int i = 0; i < 2; i++) {
                int idx = tid + i * 256;
                int n = idx >> 2, kq = (idx & 3) * 4;
                rb[i] = *(const float4*)(B + (size_t)(col0 + n) * K + kt + kq);
            }
        } else {
            #pragma unroll
            for (int i = 0; i < 2; i++) {
                int idx = tid + i * 256;
                int r = idx >> 5, nq = (idx & 31) * 4;
                rb[i] = *(const float4*)(B + (size_t)(kt + r) * N + col0 + nq);
            }
        }
    };

    load_stage(0);

    for (int kt = 0; kt < K; kt += 16) {
        // commit staged regs to smem (with tf32 convert)
        #pragma unroll
        for (int i = 0; i < 2; i++) {
            int idx = tid + i * 256;
            int r = idx >> 2, kq = (idx & 3) * 4;
            As[kq + 0][r] = to_tf32(ra[i].x);
            As[kq + 1][r] = to_tf32(ra[i].y);
            As[kq + 2][r] = to_tf32(ra[i].z);
            As[kq + 3][r] = to_tf32(ra[i].w);
        }
        if (TRANSB) {
            #pragma unroll
            for (int i = 0; i < 2; i++) {
                int idx = tid + i * 256;
                int n = idx >> 2, kq = (idx & 3) * 4;
                Bs[kq + 0][n] = to_tf32(rb[i].x);
                Bs[kq + 1][n] = to_tf32(rb[i].y);
                Bs[kq + 2][n] = to_tf32(rb[i].z);
                Bs[kq + 3][n] = to_tf32(rb[i].w);
            }
        } else {
            #pragma unroll
            for (int i = 0; i < 2; i++) {
                int idx = tid + i * 256;
                int r = idx >> 5, nq = (idx & 31) * 4;
                float4 cv;
                cv.x = to_tf32(rb[i].x); cv.y = to_tf32(rb[i].y);
                cv.z = to_tf32(rb[i].z); cv.w = to_tf32(rb[i].w);
                *(float4*)&Bs[r][nq] = cv;
            }
        }
        __syncthreads();

        if (kt + 16 < K) load_stage(kt + 16);   // prefetch next tile (overlaps mma)

        #pragma unroll
        for (int kc = 0; kc < 2; kc++) {
            const int kb = kc * 8;
            uint32_t a[4][4], b[4][2];
            #pragma unroll
            for (int mi = 0; mi < 4; mi++) {
                int m = wm + mi * 16 + g;
                a[mi][0] = __float_as_uint(As[kb + tig][m]);
                a[mi][1] = __float_as_uint(As[kb + tig][m + 8]);
                a[mi][2] = __float_as_uint(As[kb + tig + 4][m]);
                a[mi][3] = __float_as_uint(As[kb + tig + 4][m + 8]);
            }
            #pragma unroll
            for (int ni = 0; ni < 4; ni++) {
                int n = wn + ni * 8 + g;
                b[ni][0] = __float_as_uint(Bs[kb + tig][n]);
                b[ni][1] = __float_as_uint(Bs[kb + tig + 4][n]);
            }
            #pragma unroll
            for (int mi = 0; mi < 4; mi++)
                #pragma unroll
                for (int ni = 0; ni < 4; ni++)
                    mma_tf32(c[mi][ni], a[mi], b[ni]);
        }
        __syncthreads();
    }

    // epilogue
    #pragma unroll
    for (int mi = 0; mi < 4; mi++) {
        int m0 = row0 + wm + mi * 16 + g;
        #pragma unroll
        for (int ni = 0; ni < 4; ni++) {
            int n0 = col0 + wn + ni * 8 + tig * 2;
            #pragma unroll
            for (int jj = 0; jj < 4; jj++) {
                int m = m0 + (jj >> 1) * 8;
                int n = n0 + (jj & 1);
                size_t o = (size_t)m * ldc + (size_t)n * cstride;
                float v = sign * c[mi][ni][jj];
                C[o] = init ? v : (C[o] + v);
            }
        }
    }
}

// ---------------- row softmax (with score scale), in-place on S ----------------
__global__ void softmax_kernel(float* __restrict__ S) {
    // grid (SEQ, BH), 256 threads, 8 floats/thread over a 2048-wide row
    size_t base = ((size_t)blockIdx.y * SEQ + blockIdx.x) * SEQ;
    float4* row = (float4*)(S + base);
    int t = threadIdx.x;
    float4 v0 = row[t], v1 = row[t + 256];
    v0.x *= SCALE; v0.y *= SCALE; v0.z *= SCALE; v0.w *= SCALE;
    v1.x *= SCALE; v1.y *= SCALE; v1.z *= SCALE; v1.w *= SCALE;
    float m = fmaxf(fmaxf(fmaxf(v0.x, v0.y), fmaxf(v0.z, v0.w)),
                    fmaxf(fmaxf(v1.x, v1.y), fmaxf(v1.z, v1.w)));
    #pragma unroll
    for (int o = 16; o > 0; o >>= 1) m = fmaxf(m, __shfl_xor_sync(0xffffffffu, m, o));
    __shared__ float red[8];
    if ((t & 31) == 0) red[t >> 5] = m;
    __syncthreads();
    m = red[0];
    #pragma unroll
    for (int i = 1; i < 8; i++) m = fmaxf(m, red[i]);

    v0.x = expf(v0.x - m); v0.y = expf(v0.y - m); v0.z = expf(v0.z - m); v0.w = expf(v0.w - m);
    v1.x = expf(v1.x - m); v1.y = expf(v1.y - m); v1.z = expf(v1.z - m); v1.w = expf(v1.w - m);
    float s = v0.x + v0.y + v0.z + v0.w + v1.x + v1.y + v1.z + v1.w;
    #pragma unroll
    for (int o = 16; o > 0; o >>= 1) s += __shfl_xor_sync(0xffffffffu, s, o);
    __syncthreads();
    if ((t & 31) == 0) red[t >> 5] = s;
    __syncthreads();
    s = red[0];
    #pragma unroll
    for (int i = 1; i < 8; i++) s += red[i];
    float inv = 1.0f / s;
    v0.x *= inv; v0.y *= inv; v0.z *= inv; v0.w *= inv;
    v1.x *= inv; v1.y *= inv; v1.z *= inv; v1.w *= inv;
    row[t] = v0; row[t + 256] = v1;
}

// ---------------- manifold projection (complex, K=64) ----------------
__global__ void manifold_kernel(const float* __restrict__ t_re, const float* __restrict__ t_im,
                                const float* __restrict__ Wre, const float* __restrict__ Wim,
                                float* __restrict__ Tp) {
    __shared__ float sAr[16][64], sAi[16][64];
    __shared__ float4 sWr[64][16], sWi[64][16];
    int bh = blockIdx.z; int b = bh >> 3, h = bh & 7;
    int s0 = blockIdx.y * 16;
    int qbase = blockIdx.x * 16;
    int tx = threadIdx.x, ty = threadIdx.y;
    int tid = ty * 16 + tx;
    const float4* Wre4 = (const float4*)Wre;
    const float4* Wim4 = (const float4*)Wim;
    #pragma unroll
    for (int i = 0; i < 4; i++) {
        int idx = tid + i * 256;
        int ss = idx >> 6, kk = idx & 63;
        size_t gg = ((size_t)(b * SEQ + s0 + ss)) * HID + h * HDIM + kk;
        sAr[ss][kk] = t_re[gg];
        sAi[ss][kk] = t_im[gg];
        int wk = idx >> 4, mq = idx & 15;
        sWr[wk][mq] = Wre4[wk * 64 + qbase + mq];
        sWi[wk][mq] = Wim4[wk * 64 + qbase + mq];
    }
    __syncthreads();
    float4 ar = make_float4(0,0,0,0), ai = make_float4(0,0,0,0);
    #pragma unroll
    for (int k = 0; k < 64; k++) {
        float xr = sAr[ty][k], xi = sAi[ty][k];
        float4 wr = sWr[k][tx], wi = sWi[k][tx];
        ar.x += xr*wr.x - xi*wi.x;  ai.x += xr*wi.x + xi*wr.x;
        ar.y += xr*wr.y - xi*wi.y;  ai.y += xr*wi.y + xi*wr.y;
        ar.z += xr*wr.z - xi*wi.z;  ai.z += xr*wi.z + xi*wr.z;
        ar.w += xr*wr.w - xi*wi.w;  ai.w += xr*wi.w + xi*wr.w;
    }
    size_t o = ((size_t)bh * SEQ + s0 + ty) * DM + qbase * 4;
    ((float4*)(Tp + o))[tx] = ar;
    ((float4*)(Tp + o + MAN))[tx] = ai;
}

// ---------------- Wmi back-projection (complex, K=256) + head merge ----------------
__global__ void wmi_kernel(const float* __restrict__ Op,
                           const float* __restrict__ Wre, const float* __restrict__ Wim,
                           float* __restrict__ o_re, float* __restrict__ o_im) {
    __shared__ float sAr[16][64], sAi[16][64];
    __shared__ float4 sWr[64][16], sWi[64][16];
    int bh = blockIdx.y; int b = bh >> 3, h = bh & 7;
    int s0 = blockIdx.x * 16;
    int tx = threadIdx.x, ty = threadIdx.y;
    int tid = ty * 16 + tx;
    const float4* Wre4 = (const float4*)Wre;
    const float4* Wim4 = (const float4*)Wim;
    float4 ar = make_float4(0,0,0,0), ai = make_float4(0,0,0,0);
    for (int kt = 0; kt < MAN; kt += 64) {
        #pragma unroll
        for (int i = 0; i < 4; i++) {
            int idx = tid + i * 256;
            int ss = idx >> 6, kk = idx & 63;
            size_t gg = ((size_t)bh * SEQ + s0 + ss) * DM;
            sAr[ss][kk] = Op[gg + kt + kk];
            sAi[ss][kk] = Op[gg + MAN + kt + kk];
            int wk = idx >> 4, dq = idx & 15;
            sWr[wk][dq] = Wre4[(size_t)(kt + wk) * 16 + dq];
            sWi[wk][dq] = Wim4[(size_t)(kt + wk) * 16 + dq];
        }
        __syncthreads();
        #pragma unroll
        for (int k = 0; k < 64; k++) {
            float xr = sAr[ty][k], xi = sAi[ty][k];
            float4 wr = sWr[k][tx], wi = sWi[k][tx];
            ar.x += xr*wr.x - xi*wi.x;  ai.x += xr*wi.x + xi*wr.x;
            ar.y += xr*wr.y - xi*wi.y;  ai.y += xr*wi.y + xi*wr.y;
            ar.z += xr*wr.z - xi*wi.z;  ai.z += xr*wi.z + xi*wr.z;
            ar.w += xr*wr.w - xi*wi.w;  ai.w += xr*wi.w + xi*wr.w;
        }
        __syncthreads();
    }
    size_t o = ((size_t)(b * SEQ + s0 + ty)) * HID + h * HDIM;
    ((float4*)(o_re + o))[tx] = ar;
    ((float4*)(o_im + o))[tx] = ai;
}

// ---------------- launcher ----------------
extern "C" void kernel_launch(void* const* d_in, const int* in_sizes, int n_in,
                              void* d_out, int out_size) {
    const float* x      = (const float*)d_in[0];
    const float* Wq_re  = (const float*)d_in[1];
    const float* Wq_im  = (const float*)d_in[2];
    const float* Wk_re  = (const float*)d_in[3];
    const float* Wk_im  = (const float*)d_in[4];
    const float* Wv_re  = (const float*)d_in[5];
    const float* Wv_im  = (const float*)d_in[6];
    const float* Wm_re  = (const float*)d_in[7];
    const float* Wm_im  = (const float*)d_in[8];
    const float* Wmi_re = (const float*)d_in[9];
    const float* Wmi_im = (const float*)d_in[10];
    const float* Wo_re  = (const float*)d_in[11];
    const float* Wo_im  = (const float*)d_in[12];
    float* out = (float*)d_out;

    float *xn, *q_re, *q_im, *k_re, *k_im, *v_re, *v_im, *Qp, *Kp, *Vp, *Opp, *oh_re, *oh_im, *S;
    cudaGetSymbolAddress((void**)&xn,    g_xn);
    cudaGetSymbolAddress((void**)&q_re,  g_q_re);
    cudaGetSymbolAddress((void**)&q_im,  g_q_im);
    cudaGetSymbolAddress((void**)&k_re,  g_k_re);
    cudaGetSymbolAddress((void**)&k_im,  g_k_im);
    cudaGetSymbolAddress((void**)&v_re,  g_v_re);
    cudaGetSymbolAddress((void**)&v_im,  g_v_im);
    cudaGetSymbolAddress((void**)&Qp,    g_Qp);
    cudaGetSymbolAddress((void**)&Kp,    g_Kp);
    cudaGetSymbolAddress((void**)&Vp,    g_Vp);
    cudaGetSymbolAddress((void**)&Opp,   g_Op);
    cudaGetSymbolAddress((void**)&oh_re, g_oh_re);
    cudaGetSymbolAddress((void**)&oh_im, g_oh_im);
    cudaGetSymbolAddress((void**)&S,     g_S);

    norm_kernel<<<NROWS, 128>>>(x, xn);

    // QKV projections: [4096,512] x [512,512]
    dim3 tb(256);
    dim3 gq(HID / 128, NROWS / 128, 1);
    gemm_tf32<0><<<gq, tb>>>(xn, Wq_re, q_re, NROWS, HID, HID, 0, 0, 0, HID, 1, 1, 1.f);
    gemm_tf32<0><<<gq, tb>>>(xn, Wq_im, q_im, NROWS, HID, HID, 0, 0, 0, HID, 1, 1, 1.f);
    gemm_tf32<0><<<gq, tb>>>(xn, Wk_re, k_re, NROWS, HID, HID, 0, 0, 0, HID, 1, 1, 1.f);
    gemm_tf32<0><<<gq, tb>>>(xn, Wk_im, k_im, NROWS, HID, HID, 0, 0, 0, HID, 1, 1, 1.f);
    gemm_tf32<0><<<gq, tb>>>(xn, Wv_re, v_re, NROWS, HID, HID, 0, 0, 0, HID, 1, 1, 1.f);
    gemm_tf32<0><<<gq, tb>>>(xn, Wv_im, v_im, NROWS, HID, HID, 0, 0, 0, HID, 1, 1, 1.f);

    // manifold projections -> Q',K',V'  [BH, SEQ, 512]
    dim3 tb2(16, 16);
    dim3 gm(4, SEQ / 16, BH);
    manifold_kernel<<<gm, tb2>>>(q_re, q_im, Wm_re, Wm_im, Qp);
    manifold_kernel<<<gm, tb2>>>(k_re, k_im, Wm_re, Wm_im, Kp);
    manifold_kernel<<<gm, tb2>>>(v_re, v_im, Wm_re, Wm_im, Vp);

    // scores: S = Q' K'^T   (batched over BH, NT)
    gemm_tf32<1><<<dim3(SEQ / 128, SEQ / 128, BH), tb>>>(
        Qp, Kp, S, SEQ, SEQ, DM,
        (size_t)SEQ * DM, (size_t)SEQ * DM, (size_t)SEQ * SEQ, SEQ, 1, 1, 1.f);

    // softmax rows (applies SCALE)
    softmax_kernel<<<dim3(SEQ, BH), 256>>>(S);

    // O' = P V'   (batched, NN)
    gemm_tf32<0><<<dim3(DM / 128, SEQ / 128, BH), tb>>>(
        S, Vp, Opp, SEQ, DM, SEQ,
        (size_t)SEQ * SEQ, (size_t)SEQ * DM, (size_t)SEQ * DM, DM, 1, 1, 1.f);

    // Wmi back-projection + head merge
    wmi_kernel<<<dim3(SEQ / 16, BH), tb2>>>(Opp, Wmi_re, Wmi_im, oh_re, oh_im);

    // out = (oh_re + i*oh_im) @ (Wo_re + i*Wo_im), interleaved [.,512,2]
    gemm_tf32<0><<<gq, tb>>>(oh_re, Wo_re, out,     NROWS, HID, HID, 0, 0, 0, 2 * HID, 2, 1,  1.f);
    gemm_tf32<0><<<gq, tb>>>(oh_im, Wo_im, out,     NROWS, HID, HID, 0, 0, 0, 2 * HID, 2, 0, -1.f);
    gemm_tf32<0><<<gq, tb>>>(oh_re, Wo_im, out + 1, NROWS, HID, HID, 0, 0, 0, 2 * HID, 2, 1,  1.f);
    gemm_tf32<0><<<gq, tb>>>(oh_im, Wo_re, out + 1, NROWS, HID, HID, 0, 0, 0, 2 * HID, 2, 0,  1.f);
}